// round 7
// baseline (speedup 1.0000x reference)
#include <cuda_runtime.h>
#include <cuda_bf16.h>

// Word2MatEncoder: out[b] = prod_{s=0..127} M(sent[b][s]), M = 28x28 fp32.
// Associative split: 8 segments of 16 per chain (phase1, 4096 warp-tasks),
// then combine 8 partials per chain (phase2, 512 warp-tasks). 127 matmuls/chain,
// identical to reference up to fp32 regrouping (~1e-6 rel).
// Inner product: packed fp32 FFMA2 (fma.rn.f32x2), k=0 peeled into mul.rn.f32x2.
// Lane tile = 4 rows x 7 cols (28 active lanes).
// A transposed in smem (40-float rows) -> 1x LDS.128 per k per lane.
// W duplicated in smem (per-cc 20-float groups, 76-float rows)
// -> 3x LDS.128 + 1x LDS.64 per k per lane. 5 LDS per 14 FFMA2.
// W-staging smem offsets are loop-invariant -> hoisted into registers once.

#define MD 28
#define DIM 784
#define SEQ 128
#define SEGS 8
#define SEG_LEN 16
#define BATCH 512
#define WPB 2              // warps per block (2 x 12.99 KB static smem < 48 KB)
#define AT_S 40            // floats per transposed-A row (k-major), 16B-aligned
#define WD_S 76            // floats per duplicated-W row (k-major), 16B-aligned
#define WD_G 20            // floats per cc-group inside a W row

// phase-1 partial products: 512*8*784 floats = 12.8 MB static device scratch
__device__ float g_partial[BATCH * SEGS * DIM];

#define FFMA2(d, a, b, c) \
    asm("fma.rn.f32x2 %0, %1, %2, %3;" : "=l"(d) : "l"(a), "l"(b), "l"(c))
#define FMUL2(d, a, b) \
    asm("mul.rn.f32x2 %0, %1, %2;" : "=l"(d) : "l"(a), "l"(b))

union F2U { unsigned long long u; float2 f; };
union F4U { float4 f; unsigned long long u[2]; };

struct alignas(16) WarpSmem {
    float at[MD * AT_S];   // at[k*40 + i] = A[i][k]   (A = running product)
    float wd[MD * WD_S];   // wd[k*76 + 20*cc + 2*j (+1)] = W[k][7cc+j] duplicated
};

__device__ __forceinline__ void load_row(const float* __restrict__ row, float4 r[7], int lane) {
#pragma unroll
    for (int m = 0; m < 7; ++m) {
        int i4 = lane + 32 * m;                    // 196 float4 per 784-float row
        if (i4 < 196) r[m] = reinterpret_cast<const float4*>(row)[i4];
    }
}

template <int NSTEPS, bool P1>
__global__ void __launch_bounds__(WPB * 32)
chain_kernel(const int* __restrict__ sent, const float* __restrict__ table,
             float* __restrict__ out)
{
    __shared__ WarpSmem sm[WPB];
    const int warp = threadIdx.x >> 5;
    const int lane = threadIdx.x & 31;
    const int task = blockIdx.x * WPB + warp;
    WarpSmem& S = sm[warp];

    const int rg = lane >> 2;   // row group 0..6 -> rows 4rg .. 4rg+3
    const int cc = lane & 3;    // col group 0..3 -> cols 7cc .. 7cc+6
    const bool act = lane < 28;

    // Loop-invariant smem float-offsets for staging W (28 per lane), computed once.
    int wdo[28];
#pragma unroll
    for (int m = 0; m < 7; ++m) {
        int i4 = lane + 32 * m;
#pragma unroll
        for (int e = 0; e < 4; ++e) {
            if (i4 < 196) {
                int g = i4 * 4 + e;
                int k = g / MD, c = g % MD;
                wdo[m * 4 + e] = k * WD_S + WD_G * (c / 7) + 2 * (c % 7);
            } else {
                wdo[m * 4 + e] = 0;   // lane-masked below, value unused
            }
        }
    }

    auto rowptr = [&](int t) -> const float* {
        if (P1) {
            int b = task / SEGS, seg = task % SEGS;
            int idx = __ldg(&sent[b * SEQ + seg * SEG_LEN + t]);
            return table + (size_t)idx * DIM;
        } else {
            return g_partial + (size_t)(task * SEGS + t) * DIM;
        }
    };

    // stage a row held in registers into the duplicated-W layout via hoisted offsets
    auto stage_wdup = [&](const float4 r[7]) {
#pragma unroll
        for (int m = 0; m < 7; ++m) {
            if (lane + 32 * m < 196) {
                const float v[4] = {r[m].x, r[m].y, r[m].z, r[m].w};
#pragma unroll
                for (int e = 0; e < 4; ++e)
                    *reinterpret_cast<float2*>(&S.wd[wdo[m * 4 + e]]) =
                        make_float2(v[e], v[e]);
            }
        }
    };

    // init: at = transpose(M0)
    {
        const float* r0 = rowptr(0);
#pragma unroll
        for (int m = 0; m < 25; ++m) {
            int g = lane + 32 * m;
            if (g < DIM) S.at[(g % MD) * AT_S + g / MD] = r0[g];  // at[j][i] = M0[i][j]
        }
    }
    // stage M1 -> wd
    {
        float4 r1[7];
        load_row(rowptr(1), r1, lane);
        stage_wdup(r1);
    }
    __syncwarp();

    float* outrow = P1 ? (g_partial + (size_t)task * DIM)
                       : (out + (size_t)task * DIM);

#pragma unroll 1
    for (int t = 1; t < NSTEPS; ++t) {
        const bool havenext = (t + 1 < NSTEPS);

        float4 pre[7];
        if (havenext) load_row(rowptr(t + 1), pre, lane);   // LDG overlaps compute

        unsigned long long acc[2][7];

        if (act) {
            const float* at = S.at;
            const float* wd = S.wd;
#pragma unroll
            for (int k = 0; k < MD; ++k) {
                // 4 rows of A at column k: one LDS.128 (broadcast across cc lanes)
                F4U a; a.f = *reinterpret_cast<const float4*>(&at[k * AT_S + 4 * rg]);
                const unsigned long long a01 = a.u[0];
                const unsigned long long a23 = a.u[1];
                // 7 duplicated W pairs: 3x LDS.128 + 1x LDS.64 (broadcast across rg lanes)
                const float* wp = &wd[k * WD_S + WD_G * cc];
                F4U w01; w01.f = *reinterpret_cast<const float4*>(wp);       // (w0,w0,w1,w1)
                F4U w23; w23.f = *reinterpret_cast<const float4*>(wp + 4);   // (w2,w2,w3,w3)
                F4U w45; w45.f = *reinterpret_cast<const float4*>(wp + 8);   // (w4,w4,w5,w5)
                const unsigned long long w6 =
                    *reinterpret_cast<const unsigned long long*>(wp + 12);   // (w6,w6)

                if (k == 0) {
                    // peel: acc = a0 * w0 (saves the 14-mov zero-init; fma(a,b,0)==mul(a,b))
                    FMUL2(acc[0][0], a01, w01.u[0]);
                    FMUL2(acc[1][0], a23, w01.u[0]);
                    FMUL2(acc[0][1], a01, w01.u[1]);
                    FMUL2(acc[1][1], a23, w01.u[1]);
                    FMUL2(acc[0][2], a01, w23.u[0]);
                    FMUL2(acc[1][2], a23, w23.u[0]);
                    FMUL2(acc[0][3], a01, w23.u[1]);
                    FMUL2(acc[1][3], a23, w23.u[1]);
                    FMUL2(acc[0][4], a01, w45.u[0]);
                    FMUL2(acc[1][4], a23, w45.u[0]);
                    FMUL2(acc[0][5], a01, w45.u[1]);
                    FMUL2(acc[1][5], a23, w45.u[1]);
                    FMUL2(acc[0][6], a01, w6);
                    FMUL2(acc[1][6], a23, w6);
                } else {
                    FFMA2(acc[0][0], a01, w01.u[0], acc[0][0]);
                    FFMA2(acc[1][0], a23, w01.u[0], acc[1][0]);
                    FFMA2(acc[0][1], a01, w01.u[1], acc[0][1]);
                    FFMA2(acc[1][1], a23, w01.u[1], acc[1][1]);
                    FFMA2(acc[0][2], a01, w23.u[0], acc[0][2]);
                    FFMA2(acc[1][2], a23, w23.u[0], acc[1][2]);
                    FFMA2(acc[0][3], a01, w23.u[1], acc[0][3]);
                    FFMA2(acc[1][3], a23, w23.u[1], acc[1][3]);
                    FFMA2(acc[0][4], a01, w45.u[0], acc[0][4]);
                    FFMA2(acc[1][4], a23, w45.u[0], acc[1][4]);
                    FFMA2(acc[0][5], a01, w45.u[1], acc[0][5]);
                    FFMA2(acc[1][5], a23, w45.u[1], acc[1][5]);
                    FFMA2(acc[0][6], a01, w6,      acc[0][6]);
                    FFMA2(acc[1][6], a23, w6,      acc[1][6]);
                }
            }
        } else {
#pragma unroll
            for (int p = 0; p < 2; ++p)
#pragma unroll
                for (int j = 0; j < 7; ++j) acc[p][j] = 0ull;
        }
        __syncwarp();   // all lanes done reading at/wd before overwrite

        if (havenext) {
            // wd stores first (depend on LDG prefetch scoreboard -> drain early),
            // then the acc-dependent at writeback.
            stage_wdup(pre);                     // W for step t+1
            if (act) {
#pragma unroll
                for (int j = 0; j < 7; ++j)
#pragma unroll
                    for (int p = 0; p < 2; ++p) {
                        F2U u; u.u = acc[p][j];
                        *reinterpret_cast<float2*>(
                            &S.at[(7 * cc + j) * AT_S + 4 * rg + 2 * p]) = u.f;
                    }
            }
            __syncwarp();                        // writes visible before next compute
        } else if (act) {
            // final step: write row-major result straight from accumulators
#pragma unroll
            for (int p = 0; p < 2; ++p)
#pragma unroll
                for (int j = 0; j < 7; ++j) {
                    F2U u; u.u = acc[p][j];
                    outrow[(4 * rg + 2 * p + 0) * MD + 7 * cc + j] = u.f.x;
                    outrow[(4 * rg + 2 * p + 1) * MD + 7 * cc + j] = u.f.y;
                }
        }
    }
}

extern "C" void kernel_launch(void* const* d_in, const int* in_sizes, int n_in,
                              void* d_out, int out_size)
{
    const int* sent;
    const float* table;
    if (in_sizes[0] == BATCH * SEQ) {
        sent  = (const int*)d_in[0];
        table = (const float*)d_in[1];
    } else {
        sent  = (const int*)d_in[1];
        table = (const float*)d_in[0];
    }
    float* out = (float*)d_out;

    // Phase 1: 4096 segment products (8 per chain, 16 matrices each)
    chain_kernel<SEG_LEN, true><<<(BATCH * SEGS) / WPB, WPB * 32>>>(sent, table, nullptr);
    // Phase 2: combine 8 partials per chain
    chain_kernel<SEGS, false><<<BATCH / WPB, WPB * 32>>>(sent, table, out);
}